// round 7
// baseline (speedup 1.0000x reference)
#include <cuda_runtime.h>

// Shapes
// theta0: (256, 1024, 256)  idx = x0*262144 + j*256 + c
// theta1: (256, 256, 512)   idx = a*131072 + c*512 + j
// theta2: (256, 256, 512)   idx = c*131072 + b*512 + k
#define N0  67108864
#define N1  33554432
#define N2  33554432

// Scratch (device globals; fully rewritten every call -> deterministic, no zeroing)
__device__ float d_s0a[1024 * 256];      // sum over x0 of theta0  [j][c]
__device__ float d_S0p[2 * 256 * 512];   // partial sum over a of theta1 [half][c][j]
__device__ float d_S2[256 * 256];        // sum over j of theta1 [a][c]
__device__ float d_T2s[256 * 256];       // sum over k of theta2 [c][b]
__device__ float d_msg01[256 * 256];     // [a][c]
__device__ float d_msg12[256 * 256];     // [c][b]
__device__ float d_R[256 * 256];         // [c][b]  (msg21[c,j] = R[c, j>>1])
__device__ float d_Q[256 * 256];         // [a][c]  (msg10[j,c] = Q[j>>2, c])

// ---------------------------------------------------------------------------
// K1: s0a[j][c] = sum over x0 of theta0[x0, j, c].  1024 blocks (j), 256 thr (c).
__global__ void k1_reduce_t0(const float* __restrict__ t0) {
    const int j = blockIdx.x;
    const int c = threadIdx.x;
    const float* p = t0 + j * 256 + c;
    float a0 = 0.f, a1 = 0.f, a2 = 0.f, a3 = 0.f;
    #pragma unroll 4
    for (int x = 0; x < 256; x += 4) {
        a0 += p[(size_t)(x + 0) * 262144];
        a1 += p[(size_t)(x + 1) * 262144];
        a2 += p[(size_t)(x + 2) * 262144];
        a3 += p[(size_t)(x + 3) * 262144];
    }
    d_s0a[j * 256 + c] = (a0 + a1) + (a2 + a3);
}

// ---------------------------------------------------------------------------
// K2: dual reduction of theta1.
//   S0p[half][c][j] = sum over a in half of theta1[a,c,j]
//   S2[a][c]        = sum over j of theta1[a,c,j]
// grid = 512 (c*2 + half), block = 256 (8 warps), warp handles 16 'a' rows.
__global__ void k2_reduce_t1(const float* __restrict__ t1) {
    const int c    = blockIdx.x >> 1;
    const int half = blockIdx.x & 1;
    const int tid  = threadIdx.x;
    const int wid  = tid >> 5;
    const int lane = tid & 31;

    __shared__ float4 sS0[8][128];   // per-warp partials of S0 row (512 floats)

    float acc[16];
    #pragma unroll
    for (int i = 0; i < 16; i++) acc[i] = 0.f;

    #pragma unroll 2
    for (int it = 0; it < 16; it++) {
        const int a = half * 128 + wid * 16 + it;
        const float4* row = (const float4*)(t1 + (size_t)a * 131072 + (size_t)c * 512);
        float rs = 0.f;
        #pragma unroll
        for (int ch = 0; ch < 4; ch++) {
            float4 v = row[ch * 32 + lane];
            acc[ch * 4 + 0] += v.x;
            acc[ch * 4 + 1] += v.y;
            acc[ch * 4 + 2] += v.z;
            acc[ch * 4 + 3] += v.w;
            rs += (v.x + v.y) + (v.z + v.w);
        }
        #pragma unroll
        for (int off = 16; off > 0; off >>= 1)
            rs += __shfl_down_sync(0xffffffffu, rs, off);
        if (lane == 0) d_S2[a * 256 + c] = rs;
    }

    #pragma unroll
    for (int ch = 0; ch < 4; ch++)
        sS0[wid][ch * 32 + lane] = make_float4(acc[ch * 4 + 0], acc[ch * 4 + 1],
                                               acc[ch * 4 + 2], acc[ch * 4 + 3]);
    __syncthreads();

    const float* sp = (const float*)sS0;
    float s0 = 0.f, s1 = 0.f;
    #pragma unroll
    for (int w = 0; w < 8; w++) {
        s0 += sp[w * 512 + tid];
        s1 += sp[w * 512 + tid + 256];
    }
    d_S0p[half * 131072 + c * 512 + tid]       = s0;
    d_S0p[half * 131072 + c * 512 + tid + 256] = s1;
}

// ---------------------------------------------------------------------------
// K3: T2s[r] = sum over k of theta2 row r (r = c*256 + b). 8 warps/block, 1 row/warp.
__global__ void k3_reduce_t2(const float* __restrict__ t2) {
    const int r    = blockIdx.x * 8 + (threadIdx.x >> 5);
    const int lane = threadIdx.x & 31;
    const float4* row = (const float4*)(t2 + (size_t)r * 512);
    float s = 0.f;
    #pragma unroll
    for (int ch = 0; ch < 4; ch++) {
        float4 v = row[ch * 32 + lane];
        s += (v.x + v.y) + (v.z + v.w);
    }
    #pragma unroll
    for (int off = 16; off > 0; off >>= 1)
        s += __shfl_down_sync(0xffffffffu, s, off);
    if (lane == 0) d_T2s[r] = s;
}

// ---------------------------------------------------------------------------
// K4: tiny message algebra. grid = 256 (c), block = 256.
__global__ void k4_messages() {
    const int c = blockIdx.x;
    const int t = threadIdx.x;
    __shared__ float sh[256];

    // msg01[t][c] = group-of-4 sum of s0a rows
    float m01 = d_s0a[(4 * t + 0) * 256 + c] + d_s0a[(4 * t + 1) * 256 + c]
              + d_s0a[(4 * t + 2) * 256 + c] + d_s0a[(4 * t + 3) * 256 + c];
    d_msg01[t * 256 + c] = m01;

    // colsum over a of msg01[:, c]
    sh[t] = m01;
    __syncthreads();
    #pragma unroll
    for (int s = 128; s > 0; s >>= 1) {
        if (t < s) sh[t] += sh[t + s];
        __syncthreads();
    }
    const float colsum = sh[0];
    __syncthreads();

    // msg12[c][t] from s1 = S0 + colsum, pairs of j
    float s1a = d_S0p[c * 512 + 2 * t]     + d_S0p[131072 + c * 512 + 2 * t]     + colsum;
    float s1b = d_S0p[c * 512 + 2 * t + 1] + d_S0p[131072 + c * 512 + 2 * t + 1] + colsum;
    float m12 = s1a + s1b;
    d_msg12[c * 256 + t] = m12;

    // R = T2s + 511*msg12 ; S21[c] = 2 * sum_b R[c,b]
    float Rv = d_T2s[c * 256 + t] + 511.f * m12;
    d_R[c * 256 + t] = Rv;
    sh[t] = Rv;
    __syncthreads();
    #pragma unroll
    for (int s = 128; s > 0; s >>= 1) {
        if (t < s) sh[t] += sh[t + s];
        __syncthreads();
    }
    const float s21 = 2.f * sh[0];

    // Q[a][c] = S2 + 511*msg01 + S21[c]   (a = t)
    d_Q[t * 256 + c] = d_S2[t * 256 + c] + 511.f * m01 + s21;
}

// ---------------------------------------------------------------------------
// K5a: theta0_out = theta0 + Q[j>>2, c]. float4, exact map, 65536 blocks.
__global__ void k5a_out0(const float* __restrict__ t0, float* __restrict__ out) {
    const int idx4 = blockIdx.x * 256 + threadIdx.x;
    const int i = idx4 << 2;
    const int c = i & 255;
    const int j = (i >> 8) & 1023;
    float4 v = ((const float4*)t0)[idx4];
    float4 q = ((const float4*)d_Q)[((j >> 2) << 6) + (c >> 2)];
    v.x += q.x; v.y += q.y; v.z += q.z; v.w += q.w;
    ((float4*)out)[idx4] = v;
}

// K5b: theta1_out = theta1 + msg01[a,c] + R[c, j>>1]. 32768 blocks.
__global__ void k5b_out1(const float* __restrict__ t1, float* __restrict__ out) {
    const int idx4 = blockIdx.x * 256 + threadIdx.x;
    const int i = idx4 << 2;
    const int j = i & 511;
    const int c = (i >> 9) & 255;
    const int a = i >> 17;
    const float m = d_msg01[a * 256 + c];
    const float2 r = *(const float2*)&d_R[c * 256 + (j >> 1)];
    float4 v = ((const float4*)t1)[idx4];
    v.x += m + r.x; v.y += m + r.x;
    v.z += m + r.y; v.w += m + r.y;
    ((float4*)out)[idx4] = v;
}

// K5c: theta2_out = theta2 + msg12[c,b]. 32768 blocks.
__global__ void k5c_out2(const float* __restrict__ t2, float* __restrict__ out) {
    const int idx4 = blockIdx.x * 256 + threadIdx.x;
    const int i = idx4 << 2;
    const int b = (i >> 9) & 255;
    const int c = i >> 17;
    const float m = d_msg12[c * 256 + b];
    float4 v = ((const float4*)t2)[idx4];
    v.x += m; v.y += m; v.z += m; v.w += m;
    ((float4*)out)[idx4] = v;
}

// ---------------------------------------------------------------------------
extern "C" void kernel_launch(void* const* d_in, const int* in_sizes, int n_in,
                              void* d_out, int out_size) {
    const float* t0 = (const float*)d_in[0];
    const float* t1 = (const float*)d_in[1];
    const float* t2 = (const float*)d_in[2];
    float* out = (float*)d_out;

    k1_reduce_t0<<<1024, 256>>>(t0);
    k2_reduce_t1<<<512, 256>>>(t1);
    k3_reduce_t2<<<8192, 256>>>(t2);
    k4_messages<<<256, 256>>>();
    k5a_out0<<<65536, 256>>>(t0, out);
    k5b_out1<<<32768, 256>>>(t1, out + N0);
    k5c_out2<<<32768, 256>>>(t2, out + N0 + N1);
}

// round 8
// speedup vs baseline: 1.0018x; 1.0018x over previous
#include <cuda_runtime.h>

// Shapes
// theta0: (256, 1024, 256)  idx = x0*262144 + j*256 + c
// theta1: (256, 256, 512)   idx = a*131072 + c*512 + j
// theta2: (256, 256, 512)   idx = c*131072 + b*512 + k
#define N0  67108864
#define N1  33554432
#define N2  33554432

// Scratch (device globals; fully rewritten every call -> deterministic)
__device__ float d_s0a[1024 * 256];      // sum over x0 of theta0  [j][c]
__device__ float d_S0p[2 * 256 * 512];   // partial sum over a of theta1 [half][c][j]
__device__ float d_S2[256 * 256];        // sum over j of theta1 [a][c]
__device__ float d_T2s[256 * 256];       // sum over k of theta2 [c][b]
__device__ float d_msg01[256 * 256];     // [a][c]
__device__ float d_msg12[256 * 256];     // [c][b]
__device__ float d_R[256 * 256];         // [c][b]  (msg21[c,j] = R[c, j>>1])
__device__ float d_Q[256 * 256];         // [a][c]  (msg10[j,c] = Q[j>>2, c])

// ---------------------------------------------------------------------------
// KA: fused reductions of all three inputs. Block roles by blockIdx:
//   [0, 1024)     : k1  s0a[j][c] = sum_x0 theta0[x0,j,c]         (heavy: 256 KB/blk)
//   [1024, 1536)  : k2  dual reduction of theta1                  (heavy: 256 KB/blk)
//   [1536, 9728)  : k3  T2s row sums of theta2                    (light: 16 KB/blk)
// Heavy blocks first so they start in wave 0.
__global__ void KA_reduce(const float* __restrict__ t0,
                          const float* __restrict__ t1,
                          const float* __restrict__ t2) {
    const unsigned bb = blockIdx.x;

    if (bb < 1024u) {
        // ---- k1 ----
        const int j = bb;
        const int c = threadIdx.x;
        const float* p = t0 + j * 256 + c;
        float a0 = 0.f, a1 = 0.f, a2 = 0.f, a3 = 0.f;
        float a4 = 0.f, a5 = 0.f, a6 = 0.f, a7 = 0.f;
        #pragma unroll 2
        for (int x = 0; x < 256; x += 8) {
            a0 += __ldcs(p + (size_t)(x + 0) * 262144);
            a1 += __ldcs(p + (size_t)(x + 1) * 262144);
            a2 += __ldcs(p + (size_t)(x + 2) * 262144);
            a3 += __ldcs(p + (size_t)(x + 3) * 262144);
            a4 += __ldcs(p + (size_t)(x + 4) * 262144);
            a5 += __ldcs(p + (size_t)(x + 5) * 262144);
            a6 += __ldcs(p + (size_t)(x + 6) * 262144);
            a7 += __ldcs(p + (size_t)(x + 7) * 262144);
        }
        d_s0a[j * 256 + c] = ((a0 + a1) + (a2 + a3)) + ((a4 + a5) + (a6 + a7));
        return;
    }

    if (bb < 1536u) {
        // ---- k2: dual reduction of theta1 ----
        const unsigned b2 = bb - 1024u;
        const int c    = b2 >> 1;
        const int half = b2 & 1;
        const int tid  = threadIdx.x;
        const int wid  = tid >> 5;
        const int lane = tid & 31;

        __shared__ float4 sS0[8][128];

        float acc[16];
        #pragma unroll
        for (int i = 0; i < 16; i++) acc[i] = 0.f;

        #pragma unroll 2
        for (int it = 0; it < 16; it++) {
            const int a = half * 128 + wid * 16 + it;
            const float4* row = (const float4*)(t1 + (size_t)a * 131072 + (size_t)c * 512);
            float rs = 0.f;
            #pragma unroll
            for (int ch = 0; ch < 4; ch++) {
                float4 v = __ldcs(row + ch * 32 + lane);
                acc[ch * 4 + 0] += v.x;
                acc[ch * 4 + 1] += v.y;
                acc[ch * 4 + 2] += v.z;
                acc[ch * 4 + 3] += v.w;
                rs += (v.x + v.y) + (v.z + v.w);
            }
            #pragma unroll
            for (int off = 16; off > 0; off >>= 1)
                rs += __shfl_down_sync(0xffffffffu, rs, off);
            if (lane == 0) d_S2[a * 256 + c] = rs;
        }

        #pragma unroll
        for (int ch = 0; ch < 4; ch++)
            sS0[wid][ch * 32 + lane] = make_float4(acc[ch * 4 + 0], acc[ch * 4 + 1],
                                                   acc[ch * 4 + 2], acc[ch * 4 + 3]);
        __syncthreads();

        const float* sp = (const float*)sS0;
        float s0 = 0.f, s1 = 0.f;
        #pragma unroll
        for (int w = 0; w < 8; w++) {
            s0 += sp[w * 512 + tid];
            s1 += sp[w * 512 + tid + 256];
        }
        d_S0p[half * 131072 + c * 512 + tid]       = s0;
        d_S0p[half * 131072 + c * 512 + tid + 256] = s1;
        return;
    }

    // ---- k3: T2s[r] = sum_k theta2 row r ----
    const int r    = (bb - 1536u) * 8 + (threadIdx.x >> 5);
    const int lane = threadIdx.x & 31;
    const float4* row = (const float4*)(t2 + (size_t)r * 512);
    float s = 0.f;
    #pragma unroll
    for (int ch = 0; ch < 4; ch++) {
        float4 v = __ldcs(row + ch * 32 + lane);
        s += (v.x + v.y) + (v.z + v.w);
    }
    #pragma unroll
    for (int off = 16; off > 0; off >>= 1)
        s += __shfl_down_sync(0xffffffffu, s, off);
    if (lane == 0) d_T2s[r] = s;
}

// ---------------------------------------------------------------------------
// K4: tiny message algebra. grid = 256 (c), block = 256.
// Hoisted loads + warp-shuffle block reductions (4 syncthreads total).
__global__ void k4_messages() {
    const int c    = blockIdx.x;
    const int t    = threadIdx.x;
    const int lane = t & 31;
    const int wid  = t >> 5;
    __shared__ float sw[8];
    __shared__ float sbc;

    // issue all independent loads up front (MLP)
    const float v0  = d_s0a[(4 * t + 0) * 256 + c];
    const float v1  = d_s0a[(4 * t + 1) * 256 + c];
    const float v2  = d_s0a[(4 * t + 2) * 256 + c];
    const float v3  = d_s0a[(4 * t + 3) * 256 + c];
    const float2 p0 = *(const float2*)&d_S0p[c * 512 + 2 * t];
    const float2 p1 = *(const float2*)&d_S0p[131072 + c * 512 + 2 * t];
    const float t2s = d_T2s[c * 256 + t];
    const float s2  = d_S2[t * 256 + c];

    // msg01[t][c]
    const float m01 = (v0 + v1) + (v2 + v3);
    d_msg01[t * 256 + c] = m01;

    // colsum over a of msg01[:, c]
    float r = m01;
    #pragma unroll
    for (int o = 16; o > 0; o >>= 1) r += __shfl_down_sync(0xffffffffu, r, o);
    if (lane == 0) sw[wid] = r;
    __syncthreads();
    if (t == 0) {
        float s = 0.f;
        #pragma unroll
        for (int w = 0; w < 8; w++) s += sw[w];
        sbc = s;
    }
    __syncthreads();
    const float colsum = sbc;

    // msg12[c][t]
    const float m12 = (p0.x + p1.x + colsum) + (p0.y + p1.y + colsum);
    d_msg12[c * 256 + t] = m12;

    // R = T2s + 511*msg12 ; S21[c] = 2 * sum_b R[c,b]
    const float Rv = t2s + 511.f * m12;
    d_R[c * 256 + t] = Rv;

    r = Rv;
    #pragma unroll
    for (int o = 16; o > 0; o >>= 1) r += __shfl_down_sync(0xffffffffu, r, o);
    __syncthreads();                 // protect sw reuse
    if (lane == 0) sw[wid] = r;
    __syncthreads();
    if (t == 0) {
        float s = 0.f;
        #pragma unroll
        for (int w = 0; w < 8; w++) s += sw[w];
        sbc = 2.f * s;
    }
    __syncthreads();

    // Q[a][c] = S2 + 511*msg01 + S21[c]
    d_Q[t * 256 + c] = s2 + 511.f * m01 + sbc;
}

// ---------------------------------------------------------------------------
// KB: fused broadcast-add outputs. Block roles by blockIdx:
//   [0, 65536)       : theta0 + Q[j>>2, c]
//   [65536, 98304)   : theta1 + msg01[a,c] + R[c, j>>1]
//   [98304, 131072)  : theta2 + msg12[c,b]
__global__ void KB_outputs(const float* __restrict__ t0,
                           const float* __restrict__ t1,
                           const float* __restrict__ t2,
                           float* __restrict__ out) {
    const unsigned bb = blockIdx.x;

    if (bb < 65536u) {
        const int idx4 = bb * 256 + threadIdx.x;
        const int i = idx4 << 2;
        const int c = i & 255;
        const int j = (i >> 8) & 1023;
        float4 v = __ldcs((const float4*)t0 + idx4);
        float4 q = ((const float4*)d_Q)[((j >> 2) << 6) + (c >> 2)];
        v.x += q.x; v.y += q.y; v.z += q.z; v.w += q.w;
        __stcs((float4*)out + idx4, v);
        return;
    }

    if (bb < 98304u) {
        const int idx4 = (bb - 65536u) * 256 + threadIdx.x;
        const int i = idx4 << 2;
        const int j = i & 511;
        const int c = (i >> 9) & 255;
        const int a = i >> 17;
        const float m = d_msg01[a * 256 + c];
        const float2 rr = *(const float2*)&d_R[c * 256 + (j >> 1)];
        float4 v = __ldcs((const float4*)t1 + idx4);
        v.x += m + rr.x; v.y += m + rr.x;
        v.z += m + rr.y; v.w += m + rr.y;
        __stcs((float4*)(out + N0) + idx4, v);
        return;
    }

    {
        const int idx4 = (bb - 98304u) * 256 + threadIdx.x;
        const int i = idx4 << 2;
        const int b = (i >> 9) & 255;
        const int c = i >> 17;
        const float m = d_msg12[c * 256 + b];
        float4 v = __ldcs((const float4*)t2 + idx4);
        v.x += m; v.y += m; v.z += m; v.w += m;
        __stcs((float4*)(out + N0 + N1) + idx4, v);
    }
}

// ---------------------------------------------------------------------------
extern "C" void kernel_launch(void* const* d_in, const int* in_sizes, int n_in,
                              void* d_out, int out_size) {
    const float* t0 = (const float*)d_in[0];
    const float* t1 = (const float*)d_in[1];
    const float* t2 = (const float*)d_in[2];
    float* out = (float*)d_out;

    KA_reduce<<<9728, 256>>>(t0, t1, t2);
    k4_messages<<<256, 256>>>();
    KB_outputs<<<131072, 256>>>(t0, t1, t2, out);
}

// round 10
// speedup vs baseline: 1.0946x; 1.0927x over previous
#include <cuda_runtime.h>

// Shapes
// theta0: (256, 1024, 256)  idx = x0*262144 + j*256 + c
// theta1: (256, 256, 512)   idx = a*131072 + c*512 + j
// theta2: (256, 256, 512)   idx = c*131072 + b*512 + k
#define N0  67108864
#define N1  33554432
#define N2  33554432

// Scratch (device globals; fully rewritten every call -> deterministic)
__device__ float d_s0a[1024 * 256];      // sum over x0 of theta0  [j][c]
__device__ float d_S0p[2 * 256 * 512];   // partial sum over a of theta1 [half][c][j]
__device__ float d_S2[256 * 256];        // sum over j of theta1 [a][c]
__device__ float d_T2s[256 * 256];       // sum over k of theta2 [c][b]
__device__ float d_msg01[256 * 256];     // [a][c]
__device__ float d_msg12[256 * 256];     // [c][b]
__device__ float d_R[256 * 256];         // [c][b]  (msg21[c,j] = R[c, j>>1])
__device__ float d_Q[256 * 256];         // [a][c]  (msg10[j,c] = Q[j>>2, c])

// 256-bit evict_last load (sm_103a requires .v8.b32/.v4.b64 for this hint).
// Protects t2 lines in L2 across the KA->KB boundary.
__device__ __forceinline__ void ldg_evict_last_8(const float* p, float* f) {
    unsigned long long a, b, c, d;
    asm volatile("ld.global.L2::evict_last.v4.b64 {%0,%1,%2,%3}, [%4];"
                 : "=l"(a), "=l"(b), "=l"(c), "=l"(d) : "l"(p));
    *(unsigned long long*)&f[0] = a;
    *(unsigned long long*)&f[2] = b;
    *(unsigned long long*)&f[4] = c;
    *(unsigned long long*)&f[6] = d;
}

// ---------------------------------------------------------------------------
// KA: fused reductions. Block roles by blockIdx:
//   [0, 1024)     : k1  s0a[j][c] = sum_x0 theta0[x0,j,c]   (evict-first reads)
//   [1024, 1536)  : k2  dual reduction of theta1            (evict-first reads)
//   [1536, 9728)  : k3  T2s row sums of theta2              (evict_LAST reads)
// K3 is the grid tail -> t2's tail is the freshest protected data at KA's end.
__global__ void KA_reduce(const float* __restrict__ t0,
                          const float* __restrict__ t1,
                          const float* __restrict__ t2) {
    const unsigned bb = blockIdx.x;

    if (bb < 1024u) {
        // ---- k1 ----
        const int j = bb;
        const int c = threadIdx.x;
        const float* p = t0 + j * 256 + c;
        float a0 = 0.f, a1 = 0.f, a2 = 0.f, a3 = 0.f;
        float a4 = 0.f, a5 = 0.f, a6 = 0.f, a7 = 0.f;
        #pragma unroll 2
        for (int x = 0; x < 256; x += 8) {
            a0 += __ldcs(p + (size_t)(x + 0) * 262144);
            a1 += __ldcs(p + (size_t)(x + 1) * 262144);
            a2 += __ldcs(p + (size_t)(x + 2) * 262144);
            a3 += __ldcs(p + (size_t)(x + 3) * 262144);
            a4 += __ldcs(p + (size_t)(x + 4) * 262144);
            a5 += __ldcs(p + (size_t)(x + 5) * 262144);
            a6 += __ldcs(p + (size_t)(x + 6) * 262144);
            a7 += __ldcs(p + (size_t)(x + 7) * 262144);
        }
        d_s0a[j * 256 + c] = ((a0 + a1) + (a2 + a3)) + ((a4 + a5) + (a6 + a7));
        return;
    }

    if (bb < 1536u) {
        // ---- k2: dual reduction of theta1 ----
        const unsigned b2 = bb - 1024u;
        const int c    = b2 >> 1;
        const int half = b2 & 1;
        const int tid  = threadIdx.x;
        const int wid  = tid >> 5;
        const int lane = tid & 31;

        __shared__ float4 sS0[8][128];

        float acc[16];
        #pragma unroll
        for (int i = 0; i < 16; i++) acc[i] = 0.f;

        #pragma unroll 2
        for (int it = 0; it < 16; it++) {
            const int a = half * 128 + wid * 16 + it;
            const float4* row = (const float4*)(t1 + (size_t)a * 131072 + (size_t)c * 512);
            float rs = 0.f;
            #pragma unroll
            for (int ch = 0; ch < 4; ch++) {
                float4 v = __ldcs(row + ch * 32 + lane);
                acc[ch * 4 + 0] += v.x;
                acc[ch * 4 + 1] += v.y;
                acc[ch * 4 + 2] += v.z;
                acc[ch * 4 + 3] += v.w;
                rs += (v.x + v.y) + (v.z + v.w);
            }
            #pragma unroll
            for (int off = 16; off > 0; off >>= 1)
                rs += __shfl_down_sync(0xffffffffu, rs, off);
            if (lane == 0) d_S2[a * 256 + c] = rs;
        }

        #pragma unroll
        for (int ch = 0; ch < 4; ch++)
            sS0[wid][ch * 32 + lane] = make_float4(acc[ch * 4 + 0], acc[ch * 4 + 1],
                                                   acc[ch * 4 + 2], acc[ch * 4 + 3]);
        __syncthreads();

        const float* sp = (const float*)sS0;
        float s0 = 0.f, s1 = 0.f;
        #pragma unroll
        for (int w = 0; w < 8; w++) {
            s0 += sp[w * 512 + tid];
            s1 += sp[w * 512 + tid + 256];
        }
        d_S0p[half * 131072 + c * 512 + tid]       = s0;
        d_S0p[half * 131072 + c * 512 + tid + 256] = s1;
        return;
    }

    // ---- k3: T2s[r] = sum_k theta2 row r (evict_last -> stays in L2 for KB) ----
    const int r    = (bb - 1536u) * 8 + (threadIdx.x >> 5);
    const int lane = threadIdx.x & 31;
    const float* row = t2 + (size_t)r * 512;
    float f[8];
    float s = 0.f;
    #pragma unroll
    for (int ch = 0; ch < 2; ch++) {
        ldg_evict_last_8(row + (ch * 32 + lane) * 8, f);
        s += ((f[0] + f[1]) + (f[2] + f[3])) + ((f[4] + f[5]) + (f[6] + f[7]));
    }
    #pragma unroll
    for (int off = 16; off > 0; off >>= 1)
        s += __shfl_down_sync(0xffffffffu, s, off);
    if (lane == 0) d_T2s[r] = s;
}

// ---------------------------------------------------------------------------
// K4: tiny message algebra. grid = 256 (c), block = 256.
__global__ void k4_messages() {
    const int c    = blockIdx.x;
    const int t    = threadIdx.x;
    const int lane = t & 31;
    const int wid  = t >> 5;
    __shared__ float sw[8];
    __shared__ float sbc;

    const float v0  = d_s0a[(4 * t + 0) * 256 + c];
    const float v1  = d_s0a[(4 * t + 1) * 256 + c];
    const float v2  = d_s0a[(4 * t + 2) * 256 + c];
    const float v3  = d_s0a[(4 * t + 3) * 256 + c];
    const float2 p0 = *(const float2*)&d_S0p[c * 512 + 2 * t];
    const float2 p1 = *(const float2*)&d_S0p[131072 + c * 512 + 2 * t];
    const float t2s = d_T2s[c * 256 + t];
    const float s2  = d_S2[t * 256 + c];

    const float m01 = (v0 + v1) + (v2 + v3);
    d_msg01[t * 256 + c] = m01;

    float r = m01;
    #pragma unroll
    for (int o = 16; o > 0; o >>= 1) r += __shfl_down_sync(0xffffffffu, r, o);
    if (lane == 0) sw[wid] = r;
    __syncthreads();
    if (t == 0) {
        float s = 0.f;
        #pragma unroll
        for (int w = 0; w < 8; w++) s += sw[w];
        sbc = s;
    }
    __syncthreads();
    const float colsum = sbc;

    const float m12 = (p0.x + p1.x + colsum) + (p0.y + p1.y + colsum);
    d_msg12[c * 256 + t] = m12;

    const float Rv = t2s + 511.f * m12;
    d_R[c * 256 + t] = Rv;

    r = Rv;
    #pragma unroll
    for (int o = 16; o > 0; o >>= 1) r += __shfl_down_sync(0xffffffffu, r, o);
    __syncthreads();
    if (lane == 0) sw[wid] = r;
    __syncthreads();
    if (t == 0) {
        float s = 0.f;
        #pragma unroll
        for (int w = 0; w < 8; w++) s += sw[w];
        sbc = 2.f * s;
    }
    __syncthreads();

    d_Q[t * 256 + c] = s2 + 511.f * m01 + sbc;
}

// ---------------------------------------------------------------------------
// KB: fused broadcast-add outputs. Role order chosen for L2 carry-over:
//   [0, 32768)       : theta2 + msg12[c,b]   -- FIRST, reverse block order
//                      (tail of t2 is hot & protected in L2 from KA's K3)
//   [32768, 65536)   : theta1 + msg01[a,c] + R[c, j>>1]
//   [65536, 131072)  : theta0 + Q[j>>2, c]
__global__ void KB_outputs(const float* __restrict__ t0,
                           const float* __restrict__ t1,
                           const float* __restrict__ t2,
                           float* __restrict__ out) {
    const unsigned bb = blockIdx.x;

    if (bb < 32768u) {
        // reverse order: read t2 tail first (freshest L2-resident lines)
        const int idx4 = (32767 - (int)bb) * 256 + threadIdx.x;
        const int i = idx4 << 2;
        const int b = (i >> 9) & 255;
        const int c = i >> 17;
        const float m = d_msg12[c * 256 + b];
        float4 v = __ldcs((const float4*)t2 + idx4);   // hit if resident; demote after
        v.x += m; v.y += m; v.z += m; v.w += m;
        __stcs((float4*)(out + N0 + N1) + idx4, v);
        return;
    }

    if (bb < 65536u) {
        const int idx4 = (bb - 32768u) * 256 + threadIdx.x;
        const int i = idx4 << 2;
        const int j = i & 511;
        const int c = (i >> 9) & 255;
        const int a = i >> 17;
        const float m = d_msg01[a * 256 + c];
        const float2 rr = *(const float2*)&d_R[c * 256 + (j >> 1)];
        float4 v = __ldcs((const float4*)t1 + idx4);
        v.x += m + rr.x; v.y += m + rr.x;
        v.z += m + rr.y; v.w += m + rr.y;
        __stcs((float4*)(out + N0) + idx4, v);
        return;
    }

    {
        const int idx4 = (bb - 65536u) * 256 + threadIdx.x;
        const int i = idx4 << 2;
        const int c = i & 255;
        const int j = (i >> 8) & 1023;
        float4 v = __ldcs((const float4*)t0 + idx4);
        float4 q = ((const float4*)d_Q)[((j >> 2) << 6) + (c >> 2)];
        v.x += q.x; v.y += q.y; v.z += q.z; v.w += q.w;
        __stcs((float4*)out + idx4, v);
    }
}

// ---------------------------------------------------------------------------
extern "C" void kernel_launch(void* const* d_in, const int* in_sizes, int n_in,
                              void* d_out, int out_size) {
    const float* t0 = (const float*)d_in[0];
    const float* t1 = (const float*)d_in[1];
    const float* t2 = (const float*)d_in[2];
    float* out = (float*)d_out;

    KA_reduce<<<9728, 256>>>(t0, t1, t2);
    k4_messages<<<256, 256>>>();
    KB_outputs<<<131072, 256>>>(t0, t1, t2, out);
}